// round 2
// baseline (speedup 1.0000x reference)
#include <cuda_runtime.h>
#include <cuda_bf16.h>
#include <stdint.h>

#define NA 131072
#define NE 524288
#define NM 2048
#define GG 50
#define NBINS 4096
#define DCUT 6.0f
#define LN2F 0.69314718056f

// ---- device scratch (no allocations allowed) ----
__device__ float g_r[NA * 128];
__device__ float g_h[NA * 128];
__device__ float g_y[NA * 128];
__device__ float g_table[3 * (NBINS + 1) * 128];
__device__ float g_edge_d[NE];
__device__ int   g_deg[NA];
__device__ int   g_start[NA + 1];
__device__ int   g_cur[NA];
__device__ int   g_slot_other[2 * NE];
__device__ float g_slot_pos[2 * NE];

__device__ __forceinline__ float sspf(float x) {
    return fmaxf(x, 0.f) + log1pf(__expf(-fabsf(x))) - LN2F;
}

__global__ void k_prep(float* __restrict__ out) {
    int i = blockIdx.x * blockDim.x + threadIdx.x;
    if (i < NA) g_deg[i] = 0;
    if (i < NM) out[i] = 0.f;
}

__global__ void k_embed(const float* __restrict__ emb, const int* __restrict__ z) {
    int idx = blockIdx.x * blockDim.x + threadIdx.x;  // NA*32 float4 units
    int atom = idx >> 5, q = idx & 31;
    ((float4*)g_r)[(size_t)atom * 32 + q] = ((const float4*)emb)[(size_t)z[atom] * 32 + q];
}

__global__ void k_edge(const float* __restrict__ xyz, const int* __restrict__ a) {
    int e = blockIdx.x * blockDim.x + threadIdx.x;
    if (e >= NE) return;
    int i = a[2 * e], j = a[2 * e + 1];
    float dx = xyz[3 * i] - xyz[3 * j];
    float dy = xyz[3 * i + 1] - xyz[3 * j + 1];
    float dz = xyz[3 * i + 2] - xyz[3 * j + 2];
    float d = sqrtf(dx * dx + dy * dy + dz * dz);
    g_edge_d[e] = d;
    if (d < DCUT) { atomicAdd(&g_deg[i], 1); atomicAdd(&g_deg[j], 1); }
}

__global__ void k_scan() {  // 1 block, 1024 threads
    __shared__ int sh[1024];
    int tid = threadIdx.x;
    const int CH = NA / 1024;
    int base = tid * CH, s = 0;
    for (int i = 0; i < CH; i++) s += g_deg[base + i];
    sh[tid] = s;
    __syncthreads();
    for (int off = 1; off < 1024; off <<= 1) {
        int v = (tid >= off) ? sh[tid - off] : 0;
        __syncthreads();
        sh[tid] += v;
        __syncthreads();
    }
    int run = sh[tid] - s;
    for (int i = 0; i < CH; i++) {
        int dv = g_deg[base + i];
        g_start[base + i] = run;
        g_cur[base + i] = run;
        run += dv;
    }
    if (tid == 1023) g_start[NA] = run;
}

__global__ void k_fill(const int* __restrict__ a) {
    int e = blockIdx.x * blockDim.x + threadIdx.x;
    if (e >= NE) return;
    float d = g_edge_d[e];
    if (d >= DCUT) return;
    int i = a[2 * e], j = a[2 * e + 1];
    float p = d * ((float)NBINS / DCUT);
    int s0 = atomicAdd(&g_cur[i], 1);
    g_slot_other[s0] = j; g_slot_pos[s0] = p;
    int s1 = atomicAdd(&g_cur[j], 1);
    g_slot_other[s1] = i; g_slot_pos[s1] = p;
}

// table[t][b][f] = (ssp(g(d_b)@fw1+fb1)@fw2+fb2)[f] * C(d_b), 16 bins/block
__global__ __launch_bounds__(128) void k_table(const float* __restrict__ fw1,
                                               const float* __restrict__ fb1,
                                               const float* __restrict__ fw2,
                                               const float* __restrict__ fb2) {
    const int BPB = 16;
    int chunk = blockIdx.x % 257, t = blockIdx.x / 257;
    int b0 = chunk * BPB, tid = threadIdx.x;
    __shared__ float gsh[BPB * 52];
    __shared__ float t1s[BPB * 130];
    const float step = DCUT / (float)NBINS;
    const float wth = 5.0f / 49.0f;
    const float coef = -0.5f / (wth * wth);
    for (int i = tid; i < BPB * GG; i += 128) {
        int bb = i / GG, k = i % GG;
        float d = (float)(b0 + bb) * step;
        float x = d - 5.0f * (float)k / 49.0f;
        gsh[bb * 52 + k] = __expf(coef * x * x);
    }
    __syncthreads();
    const float* W1 = fw1 + (size_t)t * GG * 128;
    float s[BPB];
#pragma unroll
    for (int bb = 0; bb < BPB; bb++) s[bb] = 0.f;
    for (int k = 0; k < GG; k++) {
        float w = W1[k * 128 + tid];
#pragma unroll
        for (int bb = 0; bb < BPB; bb++) s[bb] = fmaf(gsh[bb * 52 + k], w, s[bb]);
    }
    float b1 = fb1[t * 128 + tid];
#pragma unroll
    for (int bb = 0; bb < BPB; bb++) t1s[bb * 130 + tid] = sspf(s[bb] + b1);
    __syncthreads();
    const float* W2 = fw2 + (size_t)t * 128 * 128;
    float o[BPB];
#pragma unroll
    for (int bb = 0; bb < BPB; bb++) o[bb] = 0.f;
    for (int k = 0; k < 128; k++) {
        float w = W2[k * 128 + tid];
#pragma unroll
        for (int bb = 0; bb < BPB; bb++) o[bb] = fmaf(t1s[bb * 130 + k], w, o[bb]);
    }
    float b2 = fb2[t * 128 + tid];
#pragma unroll
    for (int bb = 0; bb < BPB; bb++) {
        int b = b0 + bb;
        if (b <= NBINS) {
            float d = (float)b * step;
            float C = 0.5f * (cosf(d * 0.62831853072f) + 1.0f);
            g_table[((size_t)t * (NBINS + 1) + b) * 128 + tid] = (o[bb] + b2) * C;
        }
    }
}

// C[M,N] = epi(A[M,128] @ B[128,N] (+bias)); MODE 0: plain, 1: ssp, 2: +=residual
template <int MODE>
__global__ __launch_bounds__(256) void k_gemm(const float* __restrict__ A,
                                              const float* __restrict__ B,
                                              const float* __restrict__ bias,
                                              float* __restrict__ C, int N) {
    __shared__ float As[32 * 68];
    __shared__ float Bs[32 * 64];
    int tid = threadIdx.x;
    int tx = tid & 15, ty = tid >> 4;
    int rowBase = blockIdx.y * 64;
    int nb = blockIdx.x * 64;
    float acc[4][4] = {};
    int ar = tid >> 3, ac = (tid & 7) * 4;
    int br = tid >> 4, bc = (tid & 15) * 4;
    for (int k0 = 0; k0 < 128; k0 += 32) {
        float4 a0 = *(const float4*)&A[(size_t)(rowBase + ar) * 128 + k0 + ac];
        float4 a1 = *(const float4*)&A[(size_t)(rowBase + ar + 32) * 128 + k0 + ac];
        As[(ac + 0) * 68 + ar] = a0.x; As[(ac + 1) * 68 + ar] = a0.y;
        As[(ac + 2) * 68 + ar] = a0.z; As[(ac + 3) * 68 + ar] = a0.w;
        As[(ac + 0) * 68 + ar + 32] = a1.x; As[(ac + 1) * 68 + ar + 32] = a1.y;
        As[(ac + 2) * 68 + ar + 32] = a1.z; As[(ac + 3) * 68 + ar + 32] = a1.w;
        *(float4*)&Bs[br * 64 + bc] = *(const float4*)&B[(size_t)(k0 + br) * N + nb + bc];
        *(float4*)&Bs[(br + 16) * 64 + bc] = *(const float4*)&B[(size_t)(k0 + br + 16) * N + nb + bc];
        __syncthreads();
#pragma unroll
        for (int kk = 0; kk < 32; kk++) {
            float4 av = *(float4*)&As[kk * 68 + ty * 4];
            float4 bv = *(float4*)&Bs[kk * 64 + tx * 4];
            float aa[4] = {av.x, av.y, av.z, av.w};
            float bb[4] = {bv.x, bv.y, bv.z, bv.w};
#pragma unroll
            for (int i = 0; i < 4; i++)
#pragma unroll
                for (int j = 0; j < 4; j++) acc[i][j] = fmaf(aa[i], bb[j], acc[i][j]);
        }
        __syncthreads();
    }
#pragma unroll
    for (int i = 0; i < 4; i++) {
        int row = rowBase + ty * 4 + i;
#pragma unroll
        for (int j = 0; j < 4; j++) {
            int col = nb + tx * 4 + j;
            float v = acc[i][j];
            if (MODE > 0) v += bias[col];
            if (MODE == 1) v = sspf(v);
            if (MODE == 2) C[(size_t)row * N + col] += v;
            else           C[(size_t)row * N + col] = v;
        }
    }
}

// y[i,:] = sum over CSR slots of lerp(table, d) * h[other,:]; 1 warp per atom
__global__ __launch_bounds__(256) void k_agg(int t) {
    int gid = blockIdx.x * blockDim.x + threadIdx.x;
    int atom = gid >> 5, lane = gid & 31;
    const float4* tab4 = (const float4*)(g_table + (size_t)t * (NBINS + 1) * 128);
    const float4* h4 = (const float4*)g_h;
    int s0 = g_start[atom], s1 = g_start[atom + 1];
    float4 acc = make_float4(0, 0, 0, 0);
    for (int s = s0; s < s1; s++) {
        int j = g_slot_other[s];
        float p = g_slot_pos[s];
        int b = (int)p;
        float f = p - (float)b;
        float4 w0 = tab4[(size_t)b * 32 + lane];
        float4 w1 = tab4[(size_t)(b + 1) * 32 + lane];
        float4 hv = h4[(size_t)j * 32 + lane];
        acc.x = fmaf(fmaf(f, w1.x - w0.x, w0.x), hv.x, acc.x);
        acc.y = fmaf(fmaf(f, w1.y - w0.y, w0.y), hv.y, acc.y);
        acc.z = fmaf(fmaf(f, w1.z - w0.z, w0.z), hv.z, acc.z);
        acc.w = fmaf(fmaf(f, w1.w - w0.w, w0.w), hv.w, acc.w);
    }
    ((float4*)g_y)[(size_t)atom * 32 + lane] = acc;
}

// out[mol] += u2[atom,:] . wa2 + ba2 ; 1 warp per atom (u2 in g_h, stride 64)
__global__ __launch_bounds__(256) void k_head2(const float* __restrict__ wa2,
                                               const float* __restrict__ ba2,
                                               const int* __restrict__ mol_id,
                                               float* __restrict__ out) {
    int gid = blockIdx.x * blockDim.x + threadIdx.x;
    int atom = gid >> 5, lane = gid & 5 * 0 + (gid & 31);
    float v = g_h[(size_t)atom * 64 + lane] * wa2[lane]
            + g_h[(size_t)atom * 64 + 32 + lane] * wa2[32 + lane];
#pragma unroll
    for (int off = 16; off > 0; off >>= 1) v += __shfl_down_sync(0xffffffffu, v, off);
    if (lane == 0) atomicAdd(&out[mol_id[atom]], v + ba2[0]);
}

extern "C" void kernel_launch(void* const* d_in, const int* in_sizes, int n_in,
                              void* d_out, int out_size) {
    const float* xyz   = (const float*)d_in[0];
    const float* emb   = (const float*)d_in[1];
    const float* fw1   = (const float*)d_in[2];
    const float* fb1   = (const float*)d_in[3];
    const float* fw2   = (const float*)d_in[4];
    const float* fb2   = (const float*)d_in[5];
    const float* win   = (const float*)d_in[6];
    const float* wout1 = (const float*)d_in[7];
    const float* bout1 = (const float*)d_in[8];
    const float* wout2 = (const float*)d_in[9];
    const float* bout2 = (const float*)d_in[10];
    const float* wa1   = (const float*)d_in[11];
    const float* ba1   = (const float*)d_in[12];
    const float* wa2   = (const float*)d_in[13];
    const float* ba2   = (const float*)d_in[14];
    const int*   z     = (const int*)d_in[15];
    const int*   a     = (const int*)d_in[16];
    const int*   mol   = (const int*)d_in[17];
    float* out = (float*)d_out;

    float* r_ = nullptr; float* h_ = nullptr; float* y_ = nullptr;
    cudaGetSymbolAddress((void**)&r_, g_r);
    cudaGetSymbolAddress((void**)&h_, g_h);
    cudaGetSymbolAddress((void**)&y_, g_y);

    k_prep<<<NA / 256, 256>>>(out);
    k_embed<<<(NA * 32) / 256, 256>>>(emb, z);
    k_edge<<<NE / 256, 256>>>(xyz, a);
    k_scan<<<1, 1024>>>();
    k_fill<<<NE / 256, 256>>>(a);
    k_table<<<3 * 257, 128>>>(fw1, fb1, fw2, fb2);

    dim3 gf(2, NA / 64);
    for (int t = 0; t < 3; t++) {
        k_gemm<0><<<gf, 256>>>(r_, win + (size_t)t * 128 * 128, nullptr, h_, 128);
        k_agg<<<(NA * 32) / 256, 256>>>(t);
        k_gemm<1><<<gf, 256>>>(y_, wout1 + (size_t)t * 128 * 128, bout1 + t * 128, h_, 128);
        k_gemm<2><<<gf, 256>>>(h_, wout2 + (size_t)t * 128 * 128, bout2 + t * 128, r_, 128);
    }
    // head: u2 = ssp(r@wa1+ba1) into g_h (stride 64), then dot+segment-sum
    k_gemm<1><<<dim3(1, NA / 64), 256>>>(r_, wa1, ba1, h_, 64);
    k_head2<<<(NA * 32) / 256, 256>>>(wa2, ba2, mol, out);
}

// round 3
// speedup vs baseline: 1.6882x; 1.6882x over previous
#include <cuda_runtime.h>
#include <cuda_bf16.h>
#include <stdint.h>

#define NA 131072
#define NE 524288
#define NM 2048
#define GG 50
#define NBINS 4096
#define DCUT 6.0f
#define LN2F 0.69314718056f

// ---- device scratch ----
__device__ float g_r[NA * 128];
__device__ float g_h[NA * 128];
__device__ float g_y[NA * 128];
__device__ float g_table[3 * (NBINS + 1) * 128];
__device__ float g_edge_d[NE];
__device__ int   g_deg[NA];
__device__ int   g_start[NA + 1];
__device__ int   g_cur[NA];
__device__ int   g_bsum[512];
__device__ int   g_slot_other[2 * NE];
__device__ float g_slot_pos[2 * NE];

__device__ __forceinline__ float sspf(float x) {
    return fmaxf(x, 0.f) + log1pf(__expf(-fabsf(x))) - LN2F;
}
__device__ __forceinline__ float to_tf32(float x) {
    uint32_t o;
    asm("cvt.rna.tf32.f32 %0, %1;" : "=r"(o) : "f"(x));
    return __uint_as_float(o);
}
__device__ __forceinline__ void mma_tf32(float* c, const float* a, const float* b) {
    asm volatile(
        "mma.sync.aligned.m16n8k8.row.col.f32.tf32.tf32.f32 "
        "{%0,%1,%2,%3}, {%4,%5,%6,%7}, {%8,%9}, {%0,%1,%2,%3};"
        : "+f"(c[0]), "+f"(c[1]), "+f"(c[2]), "+f"(c[3])
        : "r"(__float_as_uint(a[0])), "r"(__float_as_uint(a[1])),
          "r"(__float_as_uint(a[2])), "r"(__float_as_uint(a[3])),
          "r"(__float_as_uint(b[0])), "r"(__float_as_uint(b[1])));
}

__global__ void k_prep(float* __restrict__ out) {
    int i = blockIdx.x * blockDim.x + threadIdx.x;
    if (i < NA) g_deg[i] = 0;
    if (i < NM) out[i] = 0.f;
}

__global__ void k_embed(const float* __restrict__ emb, const int* __restrict__ z) {
    int idx = blockIdx.x * blockDim.x + threadIdx.x;
    int atom = idx >> 5, q = idx & 31;
    ((float4*)g_r)[(size_t)atom * 32 + q] = ((const float4*)emb)[(size_t)z[atom] * 32 + q];
}

__global__ void k_edge(const float* __restrict__ xyz, const int* __restrict__ a) {
    int e = blockIdx.x * blockDim.x + threadIdx.x;
    if (e >= NE) return;
    int i = a[2 * e], j = a[2 * e + 1];
    float dx = xyz[3 * i] - xyz[3 * j];
    float dy = xyz[3 * i + 1] - xyz[3 * j + 1];
    float dz = xyz[3 * i + 2] - xyz[3 * j + 2];
    float d = sqrtf(dx * dx + dy * dy + dz * dz);
    g_edge_d[e] = d;
    if (d < DCUT) { atomicAdd(&g_deg[i], 1); atomicAdd(&g_deg[j], 1); }
}

// ---- 3-kernel scan ----
__global__ void k_scan1() {  // grid 512, block 256
    int b = blockIdx.x, t = threadIdx.x, i = b * 256 + t;
    int lane = t & 31, w = t >> 5;
    int v = g_deg[i], s = v;
#pragma unroll
    for (int off = 1; off < 32; off <<= 1) {
        int u = __shfl_up_sync(0xffffffffu, s, off);
        if (lane >= off) s += u;
    }
    __shared__ int wsum[8];
    if (lane == 31) wsum[w] = s;
    __syncthreads();
    if (t < 8) {
        int x = wsum[t];
#pragma unroll
        for (int off = 1; off < 8; off <<= 1) {
            int u = __shfl_up_sync(0xffu, x, off);
            if (t >= off) x += u;
        }
        wsum[t] = x;
    }
    __syncthreads();
    int base = (w > 0) ? wsum[w - 1] : 0;
    g_start[i] = base + s - v;           // within-block exclusive (pre-offset)
    if (t == 255) g_bsum[b] = wsum[7];
}
__global__ void k_scan2() {  // 1 block 512
    __shared__ int sh[512];
    int t = threadIdx.x;
    int v = g_bsum[t];
    sh[t] = v;
    __syncthreads();
    for (int off = 1; off < 512; off <<= 1) {
        int u = (t >= off) ? sh[t - off] : 0;
        __syncthreads();
        sh[t] += u;
        __syncthreads();
    }
    g_bsum[t] = sh[t] - v;               // exclusive
    if (t == 511) g_start[NA] = sh[511];
}
__global__ void k_scan3() {  // grid 512, block 256
    int b = blockIdx.x, i = b * 256 + threadIdx.x;
    int s = g_start[i] + g_bsum[b];
    g_start[i] = s;
    g_cur[i] = s;
}

__global__ void k_fill(const int* __restrict__ a) {
    int e = blockIdx.x * blockDim.x + threadIdx.x;
    if (e >= NE) return;
    float d = g_edge_d[e];
    if (d >= DCUT) return;
    int i = a[2 * e], j = a[2 * e + 1];
    float p = d * ((float)NBINS / DCUT);
    int s0 = atomicAdd(&g_cur[i], 1);
    g_slot_other[s0] = j; g_slot_pos[s0] = p;
    int s1 = atomicAdd(&g_cur[j], 1);
    g_slot_other[s1] = i; g_slot_pos[s1] = p;
}

// W(d)*C(d) lookup table, 16 bins per 128-thread block
__global__ __launch_bounds__(128) void k_table(const float* __restrict__ fw1,
                                               const float* __restrict__ fb1,
                                               const float* __restrict__ fw2,
                                               const float* __restrict__ fb2) {
    const int BPB = 16;
    int chunk = blockIdx.x % 257, t = blockIdx.x / 257;
    int b0 = chunk * BPB, tid = threadIdx.x;
    __shared__ float gsh[BPB * 52];
    __shared__ float t1s[BPB * 130];
    const float step = DCUT / (float)NBINS;
    const float wth = 5.0f / 49.0f;
    const float coef = -0.5f / (wth * wth);
    for (int i = tid; i < BPB * GG; i += 128) {
        int bb = i / GG, k = i % GG;
        float d = (float)(b0 + bb) * step;
        float x = d - 5.0f * (float)k / 49.0f;
        gsh[bb * 52 + k] = __expf(coef * x * x);
    }
    __syncthreads();
    const float* W1 = fw1 + (size_t)t * GG * 128;
    float s[BPB];
#pragma unroll
    for (int bb = 0; bb < BPB; bb++) s[bb] = 0.f;
    for (int k = 0; k < GG; k++) {
        float w = W1[k * 128 + tid];
#pragma unroll
        for (int bb = 0; bb < BPB; bb++) s[bb] = fmaf(gsh[bb * 52 + k], w, s[bb]);
    }
    float b1 = fb1[t * 128 + tid];
#pragma unroll
    for (int bb = 0; bb < BPB; bb++) t1s[bb * 130 + tid] = sspf(s[bb] + b1);
    __syncthreads();
    const float* W2 = fw2 + (size_t)t * 128 * 128;
    float o[BPB];
#pragma unroll
    for (int bb = 0; bb < BPB; bb++) o[bb] = 0.f;
    for (int k = 0; k < 128; k++) {
        float w = W2[k * 128 + tid];
#pragma unroll
        for (int bb = 0; bb < BPB; bb++) o[bb] = fmaf(t1s[bb * 130 + k], w, o[bb]);
    }
    float b2 = fb2[t * 128 + tid];
#pragma unroll
    for (int bb = 0; bb < BPB; bb++) {
        int b = b0 + bb;
        if (b <= NBINS) {
            float d = (float)b * step;
            float C = 0.5f * (cosf(d * 0.62831853072f) + 1.0f);
            g_table[((size_t)t * (NBINS + 1) + b) * 128 + tid] = (o[bb] + b2) * C;
        }
    }
}

// ---- tf32 tensor-core GEMM: C[128-tile,128] = epi(A[.,128]@B[128,128]) ----
// MODE 0: plain, 1: +bias,ssp, 2: +bias, C += v (residual)
template <int MODE>
__global__ __launch_bounds__(256) void k_mma(const float* __restrict__ A,
                                             const float* __restrict__ B,
                                             const float* __restrict__ bias,
                                             float* __restrict__ C) {
    __shared__ float As[128 * 36];   // [row][k] stride 36, tf32 values
    __shared__ float Bs[32 * 136];   // [k][col] stride 136
    int tid = threadIdx.x;
    int wid = tid >> 5, lane = tid & 31;
    int wm = wid & 3, wn = wid >> 2;
    int rowBase = blockIdx.x * 128;
    float acc[2][8][4];
#pragma unroll
    for (int mt = 0; mt < 2; mt++)
#pragma unroll
        for (int nt = 0; nt < 8; nt++)
#pragma unroll
            for (int c = 0; c < 4; c++) acc[mt][nt][c] = 0.f;

    int arow = tid >> 1, akq = (tid & 1) * 16;
    int brow = tid >> 3, bcq = (tid & 7) * 16;

    for (int k0 = 0; k0 < 128; k0 += 32) {
#pragma unroll
        for (int v = 0; v < 4; v++) {
            float4 av = *(const float4*)&A[(size_t)(rowBase + arow) * 128 + k0 + akq + v * 4];
            float* d = &As[arow * 36 + akq + v * 4];
            d[0] = to_tf32(av.x); d[1] = to_tf32(av.y);
            d[2] = to_tf32(av.z); d[3] = to_tf32(av.w);
        }
#pragma unroll
        for (int v = 0; v < 4; v++) {
            float4 bv = *(const float4*)&B[(size_t)(k0 + brow) * 128 + bcq + v * 4];
            float* d = &Bs[brow * 136 + bcq + v * 4];
            d[0] = to_tf32(bv.x); d[1] = to_tf32(bv.y);
            d[2] = to_tf32(bv.z); d[3] = to_tf32(bv.w);
        }
        __syncthreads();
#pragma unroll
        for (int ks = 0; ks < 4; ks++) {
            int kk = ks * 8;
            float afr[2][4];
            int ar0 = wm * 32 + (lane >> 2);
            int ac0 = kk + (lane & 3);
#pragma unroll
            for (int mt = 0; mt < 2; mt++) {
                int r = ar0 + mt * 16;
                afr[mt][0] = As[r * 36 + ac0];
                afr[mt][1] = As[(r + 8) * 36 + ac0];
                afr[mt][2] = As[r * 36 + ac0 + 4];
                afr[mt][3] = As[(r + 8) * 36 + ac0 + 4];
            }
            float bfr[8][2];
            int br0 = kk + (lane & 3);
            int bc0 = wn * 64 + (lane >> 2);
#pragma unroll
            for (int nt = 0; nt < 8; nt++) {
                bfr[nt][0] = Bs[br0 * 136 + bc0 + nt * 8];
                bfr[nt][1] = Bs[(br0 + 4) * 136 + bc0 + nt * 8];
            }
#pragma unroll
            for (int mt = 0; mt < 2; mt++)
#pragma unroll
                for (int nt = 0; nt < 8; nt++) mma_tf32(acc[mt][nt], afr[mt], bfr[nt]);
        }
        __syncthreads();
    }
    // epilogue
#pragma unroll
    for (int mt = 0; mt < 2; mt++) {
        int row0 = rowBase + wm * 32 + mt * 16 + (lane >> 2);
#pragma unroll
        for (int nt = 0; nt < 8; nt++) {
            int col = wn * 64 + nt * 8 + (lane & 3) * 2;
#pragma unroll
            for (int half = 0; half < 2; half++) {
                int row = row0 + half * 8;
#pragma unroll
                for (int q = 0; q < 2; q++) {
                    float v = acc[mt][nt][half * 2 + q];
                    if (MODE > 0) v += bias[col + q];
                    if (MODE == 1) v = sspf(v);
                    size_t idx = (size_t)row * 128 + col + q;
                    if (MODE == 2) C[idx] += v;
                    else           C[idx] = v;
                }
            }
        }
    }
}

// SIMT GEMM kept for the head (N=64): C = ssp(A@B + bias)
__global__ __launch_bounds__(256) void k_gemm_head(const float* __restrict__ A,
                                                   const float* __restrict__ B,
                                                   const float* __restrict__ bias,
                                                   float* __restrict__ C, int N) {
    __shared__ float As[32 * 68];
    __shared__ float Bs[32 * 64];
    int tid = threadIdx.x;
    int tx = tid & 15, ty = tid >> 4;
    int rowBase = blockIdx.y * 64;
    int nb = blockIdx.x * 64;
    float acc[4][4] = {};
    int ar = tid >> 3, ac = (tid & 7) * 4;
    int br = tid >> 4, bc = (tid & 15) * 4;
    for (int k0 = 0; k0 < 128; k0 += 32) {
        float4 a0 = *(const float4*)&A[(size_t)(rowBase + ar) * 128 + k0 + ac];
        float4 a1 = *(const float4*)&A[(size_t)(rowBase + ar + 32) * 128 + k0 + ac];
        As[(ac + 0) * 68 + ar] = a0.x; As[(ac + 1) * 68 + ar] = a0.y;
        As[(ac + 2) * 68 + ar] = a0.z; As[(ac + 3) * 68 + ar] = a0.w;
        As[(ac + 0) * 68 + ar + 32] = a1.x; As[(ac + 1) * 68 + ar + 32] = a1.y;
        As[(ac + 2) * 68 + ar + 32] = a1.z; As[(ac + 3) * 68 + ar + 32] = a1.w;
        *(float4*)&Bs[br * 64 + bc] = *(const float4*)&B[(size_t)(k0 + br) * N + nb + bc];
        *(float4*)&Bs[(br + 16) * 64 + bc] = *(const float4*)&B[(size_t)(k0 + br + 16) * N + nb + bc];
        __syncthreads();
#pragma unroll
        for (int kk = 0; kk < 32; kk++) {
            float4 av = *(float4*)&As[kk * 68 + ty * 4];
            float4 bv = *(float4*)&Bs[kk * 64 + tx * 4];
            float aa[4] = {av.x, av.y, av.z, av.w};
            float bb[4] = {bv.x, bv.y, bv.z, bv.w};
#pragma unroll
            for (int i = 0; i < 4; i++)
#pragma unroll
                for (int j = 0; j < 4; j++) acc[i][j] = fmaf(aa[i], bb[j], acc[i][j]);
        }
        __syncthreads();
    }
#pragma unroll
    for (int i = 0; i < 4; i++) {
        int row = rowBase + ty * 4 + i;
#pragma unroll
        for (int j = 0; j < 4; j++) {
            int col = nb + tx * 4 + j;
            C[(size_t)row * N + col] = sspf(acc[i][j] + bias[col]);
        }
    }
}

// y[i,:] = sum over CSR slots of lerp(table,d) * h[other,:]; 1 warp per atom
__global__ __launch_bounds__(256) void k_agg(int t) {
    int gid = blockIdx.x * blockDim.x + threadIdx.x;
    int atom = gid >> 5, lane = gid & 31;
    const float4* tab4 = (const float4*)(g_table + (size_t)t * (NBINS + 1) * 128);
    const float4* h4 = (const float4*)g_h;
    int s0 = g_start[atom], s1 = g_start[atom + 1];
    float4 acc = make_float4(0, 0, 0, 0);
    for (int s = s0; s < s1; s++) {
        int j = g_slot_other[s];
        float p = g_slot_pos[s];
        int b = (int)p;
        float f = p - (float)b;
        float4 w0 = tab4[(size_t)b * 32 + lane];
        float4 w1 = tab4[(size_t)(b + 1) * 32 + lane];
        float4 hv = h4[(size_t)j * 32 + lane];
        acc.x = fmaf(fmaf(f, w1.x - w0.x, w0.x), hv.x, acc.x);
        acc.y = fmaf(fmaf(f, w1.y - w0.y, w0.y), hv.y, acc.y);
        acc.z = fmaf(fmaf(f, w1.z - w0.z, w0.z), hv.z, acc.z);
        acc.w = fmaf(fmaf(f, w1.w - w0.w, w0.w), hv.w, acc.w);
    }
    ((float4*)g_y)[(size_t)atom * 32 + lane] = acc;
}

__global__ __launch_bounds__(256) void k_head2(const float* __restrict__ wa2,
                                               const float* __restrict__ ba2,
                                               const int* __restrict__ mol_id,
                                               float* __restrict__ out) {
    int gid = blockIdx.x * blockDim.x + threadIdx.x;
    int atom = gid >> 5, lane = gid & 31;
    float v = g_h[(size_t)atom * 64 + lane] * wa2[lane]
            + g_h[(size_t)atom * 64 + 32 + lane] * wa2[32 + lane];
#pragma unroll
    for (int off = 16; off > 0; off >>= 1) v += __shfl_down_sync(0xffffffffu, v, off);
    if (lane == 0) atomicAdd(&out[mol_id[atom]], v + ba2[0]);
}

extern "C" void kernel_launch(void* const* d_in, const int* in_sizes, int n_in,
                              void* d_out, int out_size) {
    const float* xyz   = (const float*)d_in[0];
    const float* emb   = (const float*)d_in[1];
    const float* fw1   = (const float*)d_in[2];
    const float* fb1   = (const float*)d_in[3];
    const float* fw2   = (const float*)d_in[4];
    const float* fb2   = (const float*)d_in[5];
    const float* win   = (const float*)d_in[6];
    const float* wout1 = (const float*)d_in[7];
    const float* bout1 = (const float*)d_in[8];
    const float* wout2 = (const float*)d_in[9];
    const float* bout2 = (const float*)d_in[10];
    const float* wa1   = (const float*)d_in[11];
    const float* ba1   = (const float*)d_in[12];
    const float* wa2   = (const float*)d_in[13];
    const float* ba2   = (const float*)d_in[14];
    const int*   z     = (const int*)d_in[15];
    const int*   a     = (const int*)d_in[16];
    const int*   mol   = (const int*)d_in[17];
    float* out = (float*)d_out;

    float* r_ = nullptr; float* h_ = nullptr; float* y_ = nullptr;
    cudaGetSymbolAddress((void**)&r_, g_r);
    cudaGetSymbolAddress((void**)&h_, g_h);
    cudaGetSymbolAddress((void**)&y_, g_y);

    k_prep<<<NA / 256, 256>>>(out);
    k_embed<<<(NA * 32) / 256, 256>>>(emb, z);
    k_edge<<<NE / 256, 256>>>(xyz, a);
    k_scan1<<<512, 256>>>();
    k_scan2<<<1, 512>>>();
    k_scan3<<<512, 256>>>();
    k_fill<<<NE / 256, 256>>>(a);
    k_table<<<3 * 257, 128>>>(fw1, fb1, fw2, fb2);

    for (int t = 0; t < 3; t++) {
        k_mma<0><<<NA / 128, 256>>>(r_, win + (size_t)t * 128 * 128, nullptr, h_);
        k_agg<<<(NA * 32) / 256, 256>>>(t);
        k_mma<1><<<NA / 128, 256>>>(y_, wout1 + (size_t)t * 128 * 128, bout1 + t * 128, h_);
        k_mma<2><<<NA / 128, 256>>>(h_, wout2 + (size_t)t * 128 * 128, bout2 + t * 128, r_);
    }
    k_gemm_head<<<dim3(1, NA / 64), 256>>>(r_, wa1, ba1, h_, 64);
    k_head2<<<(NA * 32) / 256, 256>>>(wa2, ba2, mol, out);
}

// round 6
// speedup vs baseline: 2.2777x; 1.3492x over previous
#include <cuda_runtime.h>
#include <cuda_bf16.h>
#include <stdint.h>

#define NA 131072
#define NE 524288
#define NM 2048
#define GG 50
#define NBINS 4096
#define DCUT 6.0f
#define LN2F 0.69314718056f
#define STR 132   // smem row stride in words; 132 % 32 == 4 -> conflict-free fragments

// ---- device scratch ----
__device__ float g_r[NA * 128];
__device__ float g_h[NA * 128];
__device__ float g_y[NA * 128];
__device__ float g_wTf[10 * 128 * 128];   // transposed, tf32-rounded weights [m][n][k]
__device__ float g_table[3 * (NBINS + 1) * 128];
__device__ float g_edge_d[NE];
__device__ int   g_deg[NA];
__device__ int   g_start[NA + 1];
__device__ int   g_cur[NA];
__device__ int   g_bsum[512];
__device__ int   g_slot_other[2 * NE];
__device__ float g_slot_pos[2 * NE];

__device__ __forceinline__ float sspf(float x) {
    return fmaxf(x, 0.f) + log1pf(__expf(-fabsf(x))) - LN2F;
}
__device__ __forceinline__ float to_tf32(float x) {
    uint32_t o;
    asm("cvt.rna.tf32.f32 %0, %1;" : "=r"(o) : "f"(x));
    return __uint_as_float(o);
}
__device__ __forceinline__ void mma_tf32(float* c, const float* a, const float* b) {
    asm volatile(
        "mma.sync.aligned.m16n8k8.row.col.f32.tf32.tf32.f32 "
        "{%0,%1,%2,%3}, {%4,%5,%6,%7}, {%8,%9}, {%0,%1,%2,%3};"
        : "+f"(c[0]), "+f"(c[1]), "+f"(c[2]), "+f"(c[3])
        : "r"(__float_as_uint(a[0])), "r"(__float_as_uint(a[1])),
          "r"(__float_as_uint(a[2])), "r"(__float_as_uint(a[3])),
          "r"(__float_as_uint(b[0])), "r"(__float_as_uint(b[1])));
}

// ---- prep kernels ----
__global__ void k_prep(float* __restrict__ out) {
    int i = blockIdx.x * blockDim.x + threadIdx.x;
    if (i < NA) g_deg[i] = 0;
    if (i < NM) out[i] = 0.f;
}
__global__ void k_embed(const float* __restrict__ emb, const int* __restrict__ z) {
    int idx = blockIdx.x * blockDim.x + threadIdx.x;
    int atom = idx >> 5, q = idx & 31;
    ((float4*)g_r)[(size_t)atom * 32 + q] = ((const float4*)emb)[(size_t)z[atom] * 32 + q];
}
__global__ void k_edge(const float* __restrict__ xyz, const int* __restrict__ a) {
    int e = blockIdx.x * blockDim.x + threadIdx.x;
    if (e >= NE) return;
    int i = a[2 * e], j = a[2 * e + 1];
    float dx = xyz[3 * i] - xyz[3 * j];
    float dy = xyz[3 * i + 1] - xyz[3 * j + 1];
    float dz = xyz[3 * i + 2] - xyz[3 * j + 2];
    float d = sqrtf(dx * dx + dy * dy + dz * dz);
    g_edge_d[e] = d;
    if (d < DCUT) { atomicAdd(&g_deg[i], 1); atomicAdd(&g_deg[j], 1); }
}
__global__ void k_scan1() {
    int b = blockIdx.x, t = threadIdx.x, i = b * 256 + t;
    int lane = t & 31, w = t >> 5;
    int v = g_deg[i], s = v;
#pragma unroll
    for (int off = 1; off < 32; off <<= 1) {
        int u = __shfl_up_sync(0xffffffffu, s, off);
        if (lane >= off) s += u;
    }
    __shared__ int wsum[8];
    if (lane == 31) wsum[w] = s;
    __syncthreads();
    if (t < 8) {
        int x = wsum[t];
#pragma unroll
        for (int off = 1; off < 8; off <<= 1) {
            int u = __shfl_up_sync(0xffu, x, off);
            if (t >= off) x += u;
        }
        wsum[t] = x;
    }
    __syncthreads();
    int base = (w > 0) ? wsum[w - 1] : 0;
    g_start[i] = base + s - v;
    if (t == 255) g_bsum[b] = wsum[7];
}
__global__ void k_scan2() {
    __shared__ int sh[512];
    int t = threadIdx.x;
    int v = g_bsum[t];
    sh[t] = v;
    __syncthreads();
    for (int off = 1; off < 512; off <<= 1) {
        int u = (t >= off) ? sh[t - off] : 0;
        __syncthreads();
        sh[t] += u;
        __syncthreads();
    }
    g_bsum[t] = sh[t] - v;
    if (t == 511) g_start[NA] = sh[511];
}
__global__ void k_scan3() {
    int b = blockIdx.x, i = b * 256 + threadIdx.x;
    int s = g_start[i] + g_bsum[b];
    g_start[i] = s;
    g_cur[i] = s;
}
__global__ void k_fill(const int* __restrict__ a) {
    int e = blockIdx.x * blockDim.x + threadIdx.x;
    if (e >= NE) return;
    float d = g_edge_d[e];
    if (d >= DCUT) return;
    int i = a[2 * e], j = a[2 * e + 1];
    float p = d * ((float)NBINS / DCUT);
    int s0 = atomicAdd(&g_cur[i], 1);
    g_slot_other[s0] = j; g_slot_pos[s0] = p;
    int s1 = atomicAdd(&g_cur[j], 1);
    g_slot_other[s1] = i; g_slot_pos[s1] = p;
}

// transpose + tf32-round weights: g_wTf[m][n*128+k]
__global__ void k_wconv(const float* __restrict__ win, const float* __restrict__ wout1,
                        const float* __restrict__ wout2, const float* __restrict__ wa1) {
    int idx = blockIdx.x * blockDim.x + threadIdx.x;  // 640*256
    int m = idx >> 14, pos = idx & 16383;
    if (m < 9) {
        int n = pos >> 7, k = pos & 127;
        const float* src = (m < 3) ? win + (size_t)m * 16384
                         : (m < 6) ? wout1 + (size_t)(m - 3) * 16384
                                   : wout2 + (size_t)(m - 6) * 16384;
        g_wTf[idx] = to_tf32(src[k * 128 + n]);
    } else if (m == 9 && pos < 8192) {
        int n = pos >> 7, k = pos & 127;
        g_wTf[(size_t)9 * 16384 + pos] = to_tf32(wa1[k * 64 + n]);
    }
}

// W(d)*C(d) table
__global__ __launch_bounds__(128) void k_table(const float* __restrict__ fw1,
                                               const float* __restrict__ fb1,
                                               const float* __restrict__ fw2,
                                               const float* __restrict__ fb2) {
    const int BPB = 16;
    int chunk = blockIdx.x % 257, t = blockIdx.x / 257;
    int b0 = chunk * BPB, tid = threadIdx.x;
    __shared__ float gsh[BPB * 52];
    __shared__ float t1s[BPB * 130];
    const float step = DCUT / (float)NBINS;
    const float wth = 5.0f / 49.0f;
    const float coef = -0.5f / (wth * wth);
    for (int i = tid; i < BPB * GG; i += 128) {
        int bb = i / GG, k = i % GG;
        float d = (float)(b0 + bb) * step;
        float x = d - 5.0f * (float)k / 49.0f;
        gsh[bb * 52 + k] = __expf(coef * x * x);
    }
    __syncthreads();
    const float* W1 = fw1 + (size_t)t * GG * 128;
    float s[BPB];
#pragma unroll
    for (int bb = 0; bb < BPB; bb++) s[bb] = 0.f;
    for (int k = 0; k < GG; k++) {
        float w = W1[k * 128 + tid];
#pragma unroll
        for (int bb = 0; bb < BPB; bb++) s[bb] = fmaf(gsh[bb * 52 + k], w, s[bb]);
    }
    float b1 = fb1[t * 128 + tid];
#pragma unroll
    for (int bb = 0; bb < BPB; bb++) t1s[bb * 130 + tid] = sspf(s[bb] + b1);
    __syncthreads();
    const float* W2 = fw2 + (size_t)t * 128 * 128;
    float o[BPB];
#pragma unroll
    for (int bb = 0; bb < BPB; bb++) o[bb] = 0.f;
    for (int k = 0; k < 128; k++) {
        float w = W2[k * 128 + tid];
#pragma unroll
        for (int bb = 0; bb < BPB; bb++) o[bb] = fmaf(t1s[bb * 130 + k], w, o[bb]);
    }
    float b2 = fb2[t * 128 + tid];
#pragma unroll
    for (int bb = 0; bb < BPB; bb++) {
        int b = b0 + bb;
        if (b <= NBINS) {
            float d = (float)b * step;
            float C = 0.5f * (cosf(d * 0.62831853072f) + 1.0f);
            g_table[((size_t)t * (NBINS + 1) + b) * 128 + tid] = (o[bb] + b2) * C;
        }
    }
}

// ---- tf32 mma building blocks (full-K smem tiles) ----
template <int ROWS, bool CVT>
__device__ __forceinline__ void load_tile(float* dst, const float* src, int tid) {
#pragma unroll
    for (int i = 0; i < ROWS * 128 / 1024; i++) {
        int idx = tid + i * 256;
        int row = idx >> 5, q = idx & 31;
        float4 v = *(const float4*)&src[(size_t)row * 128 + q * 4];
        if (CVT) {
            v.x = to_tf32(v.x); v.y = to_tf32(v.y);
            v.z = to_tf32(v.z); v.w = to_tf32(v.w);
        }
        *(float4*)&dst[row * STR + q * 4] = v;
    }
}
template <int NT>
__device__ __forceinline__ void mma_tile(float acc[][NT][4], const float* As,
                                         const float* Bs, int wm, int wn, int lane) {
#pragma unroll
    for (int ks = 0; ks < 16; ks++) {
        int k = ks * 8 + (lane & 3);
        int r0 = wm * 32 + (lane >> 2);
        float af[2][4];
#pragma unroll
        for (int mt = 0; mt < 2; mt++) {
            int r = r0 + mt * 16;
            af[mt][0] = As[r * STR + k];
            af[mt][1] = As[(r + 8) * STR + k];
            af[mt][2] = As[r * STR + k + 4];
            af[mt][3] = As[(r + 8) * STR + k + 4];
        }
        float bf[NT][2];
#pragma unroll
        for (int nt = 0; nt < NT; nt++) {
            int n = wn * (NT * 8) + nt * 8 + (lane >> 2);
            bf[nt][0] = Bs[n * STR + k];
            bf[nt][1] = Bs[n * STR + k + 4];
        }
#pragma unroll
        for (int mt = 0; mt < 2; mt++)
#pragma unroll
            for (int nt = 0; nt < NT; nt++) mma_tf32(acc[mt][nt], af[mt], bf[nt]);
    }
}

// h = r @ win[t]
__global__ __launch_bounds__(256) void k_mma_h(int t) {
    extern __shared__ float sm[];
    float* As = sm;
    float* Bs = sm + 128 * STR;
    int tid = threadIdx.x, lane = tid & 31, wid = tid >> 5, wm = wid & 3, wn = wid >> 2;
    load_tile<128, true>(As, g_r + (size_t)blockIdx.x * 16384, tid);
    load_tile<128, false>(Bs, g_wTf + (size_t)t * 16384, tid);
    __syncthreads();
    float acc[2][8][4] = {};
    mma_tile<8>(acc, As, Bs, wm, wn, lane);
    float* H = g_h + (size_t)blockIdx.x * 16384;
#pragma unroll
    for (int mt = 0; mt < 2; mt++) {
        int r0 = wm * 32 + mt * 16 + (lane >> 2);
#pragma unroll
        for (int nt = 0; nt < 8; nt++) {
            int col = wn * 64 + nt * 8 + (lane & 3) * 2;
            *(float2*)&H[r0 * 128 + col] = make_float2(acc[mt][nt][0], acc[mt][nt][1]);
            *(float2*)&H[(r0 + 8) * 128 + col] = make_float2(acc[mt][nt][2], acc[mt][nt][3]);
        }
    }
}

// fused: r += ssp(y@W1+b1)@W2+b2
__global__ __launch_bounds__(256) void k_dr(int t, const float* __restrict__ b1,
                                            const float* __restrict__ b2) {
    extern __shared__ float sm[];
    float* As = sm;
    float* Bs = sm + 128 * STR;
    int tid = threadIdx.x, lane = tid & 31, wid = tid >> 5, wm = wid & 3, wn = wid >> 2;
    load_tile<128, true>(As, g_y + (size_t)blockIdx.x * 16384, tid);
    load_tile<128, false>(Bs, g_wTf + (size_t)(3 + t) * 16384, tid);
    __syncthreads();
    float acc[2][8][4] = {};
    mma_tile<8>(acc, As, Bs, wm, wn, lane);
    __syncthreads();   // GEMM1 fully done before As/Bs overwritten
#pragma unroll
    for (int mt = 0; mt < 2; mt++) {
        int r0 = wm * 32 + mt * 16 + (lane >> 2);
#pragma unroll
        for (int nt = 0; nt < 8; nt++) {
            int col = wn * 64 + nt * 8 + (lane & 3) * 2;
            float bb0 = b1[col], bb1 = b1[col + 1];
            As[r0 * STR + col]           = to_tf32(sspf(acc[mt][nt][0] + bb0));
            As[r0 * STR + col + 1]       = to_tf32(sspf(acc[mt][nt][1] + bb1));
            As[(r0 + 8) * STR + col]     = to_tf32(sspf(acc[mt][nt][2] + bb0));
            As[(r0 + 8) * STR + col + 1] = to_tf32(sspf(acc[mt][nt][3] + bb1));
        }
    }
    load_tile<128, false>(Bs, g_wTf + (size_t)(6 + t) * 16384, tid);
    __syncthreads();
    float acc2[2][8][4] = {};
    mma_tile<8>(acc2, As, Bs, wm, wn, lane);
    float* R = g_r + (size_t)blockIdx.x * 16384;
#pragma unroll
    for (int mt = 0; mt < 2; mt++) {
        int r0 = wm * 32 + mt * 16 + (lane >> 2);
#pragma unroll
        for (int nt = 0; nt < 8; nt++) {
            int col = wn * 64 + nt * 8 + (lane & 3) * 2;
            float bb0 = b2[col], bb1 = b2[col + 1];
            R[r0 * 128 + col]           += acc2[mt][nt][0] + bb0;
            R[r0 * 128 + col + 1]       += acc2[mt][nt][1] + bb1;
            R[(r0 + 8) * 128 + col]     += acc2[mt][nt][2] + bb0;
            R[(r0 + 8) * 128 + col + 1] += acc2[mt][nt][3] + bb1;
        }
    }
}

// fused head: out[mol] += ssp(r@wa1+ba1)·wa2 + ba2
__global__ __launch_bounds__(256) void k_head(const float* __restrict__ ba1,
                                              const float* __restrict__ wa2,
                                              const float* __restrict__ ba2,
                                              const int* __restrict__ mol,
                                              float* __restrict__ out) {
    extern __shared__ float sm[];
    float* As = sm;
    float* Bs = sm + 128 * STR;
    float* sred = sm + 128 * STR + 64 * STR;   // 128 floats
    int tid = threadIdx.x, lane = tid & 31, wid = tid >> 5, wm = wid & 3, wn = wid >> 2;
    load_tile<128, true>(As, g_r + (size_t)blockIdx.x * 16384, tid);
    load_tile<64, false>(Bs, g_wTf + (size_t)9 * 16384, tid);
    if (tid < 128) sred[tid] = 0.f;
    __syncthreads();
    float acc[2][4][4] = {};
    mma_tile<4>(acc, As, Bs, wm, wn, lane);
#pragma unroll
    for (int mt = 0; mt < 2; mt++) {
        int r0 = wm * 32 + mt * 16 + (lane >> 2);
        float p0 = 0.f, p1 = 0.f;
#pragma unroll
        for (int nt = 0; nt < 4; nt++) {
            int col = wn * 32 + nt * 8 + (lane & 3) * 2;
            float bb0 = ba1[col], bb1 = ba1[col + 1];
            float w0 = wa2[col], w1 = wa2[col + 1];
            p0 += sspf(acc[mt][nt][0] + bb0) * w0 + sspf(acc[mt][nt][1] + bb1) * w1;
            p1 += sspf(acc[mt][nt][2] + bb0) * w0 + sspf(acc[mt][nt][3] + bb1) * w1;
        }
        atomicAdd(&sred[r0], p0);
        atomicAdd(&sred[r0 + 8], p1);
    }
    __syncthreads();
    if (tid < 128)
        atomicAdd(&out[mol[blockIdx.x * 128 + tid]], sred[tid] + ba2[0]);
}

// y[i,:] = sum lerp(table,d) * h[other,:]; 1 warp per atom (fp32)
__global__ __launch_bounds__(256) void k_agg(int t) {
    int gid = blockIdx.x * blockDim.x + threadIdx.x;
    int atom = gid >> 5, lane = gid & 31;
    const float4* tab4 = (const float4*)(g_table + (size_t)t * (NBINS + 1) * 128);
    const float4* h4 = (const float4*)g_h;
    int s0 = g_start[atom], s1 = g_start[atom + 1];
    float4 acc = make_float4(0, 0, 0, 0);
    for (int s = s0; s < s1; s++) {
        int j = g_slot_other[s];
        float p = g_slot_pos[s];
        int b = (int)p;
        float f = p - (float)b;
        float4 w0 = tab4[(size_t)b * 32 + lane];
        float4 w1 = tab4[(size_t)(b + 1) * 32 + lane];
        float4 hv = h4[(size_t)j * 32 + lane];
        acc.x = fmaf(fmaf(f, w1.x - w0.x, w0.x), hv.x, acc.x);
        acc.y = fmaf(fmaf(f, w1.y - w0.y, w0.y), hv.y, acc.y);
        acc.z = fmaf(fmaf(f, w1.z - w0.z, w0.z), hv.z, acc.z);
        acc.w = fmaf(fmaf(f, w1.w - w0.w, w0.w), hv.w, acc.w);
    }
    ((float4*)g_y)[(size_t)atom * 32 + lane] = acc;
}

extern "C" void kernel_launch(void* const* d_in, const int* in_sizes, int n_in,
                              void* d_out, int out_size) {
    const float* xyz   = (const float*)d_in[0];
    const float* emb   = (const float*)d_in[1];
    const float* fw1   = (const float*)d_in[2];
    const float* fb1   = (const float*)d_in[3];
    const float* fw2   = (const float*)d_in[4];
    const float* fb2   = (const float*)d_in[5];
    const float* win   = (const float*)d_in[6];
    const float* wout1 = (const float*)d_in[7];
    const float* bout1 = (const float*)d_in[8];
    const float* wout2 = (const float*)d_in[9];
    const float* bout2 = (const float*)d_in[10];
    const float* wa1   = (const float*)d_in[11];
    const float* ba1   = (const float*)d_in[12];
    const float* wa2   = (const float*)d_in[13];
    const float* ba2   = (const float*)d_in[14];
    const int*   z     = (const int*)d_in[15];
    const int*   a     = (const int*)d_in[16];
    const int*   mol   = (const int*)d_in[17];
    float* out = (float*)d_out;

    const int SM_BIG  = 2 * 128 * STR * 4;                    // 135168
    const int SM_HEAD = (128 * STR + 64 * STR + 128) * 4;     // 101888
    cudaFuncSetAttribute(k_mma_h, cudaFuncAttributeMaxDynamicSharedMemorySize, SM_BIG);
    cudaFuncSetAttribute(k_dr, cudaFuncAttributeMaxDynamicSharedMemorySize, SM_BIG);
    cudaFuncSetAttribute(k_head, cudaFuncAttributeMaxDynamicSharedMemorySize, SM_HEAD);

    k_prep<<<NA / 256, 256>>>(out);
    k_embed<<<(NA * 32) / 256, 256>>>(emb, z);
    k_edge<<<NE / 256, 256>>>(xyz, a);
    k_scan1<<<512, 256>>>();
    k_scan2<<<1, 512>>>();
    k_scan3<<<512, 256>>>();
    k_fill<<<NE / 256, 256>>>(a);
    k_table<<<3 * 257, 128>>>(fw1, fb1, fw2, fb2);
    k_wconv<<<640, 256>>>(win, wout1, wout2, wa1);

    for (int t = 0; t < 3; t++) {
        k_mma_h<<<NA / 128, 256, SM_BIG>>>(t);
        k_agg<<<(NA * 32) / 256, 256>>>(t);
        k_dr<<<NA / 128, 256, SM_BIG>>>(t, bout1 + t * 128, bout2 + t * 128);
    }
    k_head<<<NA / 128, 256, SM_HEAD>>>(ba1, wa2, ba2, mol, out);
}